// round 8
// baseline (speedup 1.0000x reference)
#include <cuda_runtime.h>
#include <cuda_bf16.h>
#include <cstdint>

// Problem constants (fixed by the reference)
#define B_SEG   16
#define D_F     128            // fine feature dim  (32 float4, 512 B/row)
#define D_C     256            // coarse feature dim (64 float4, 1024 B/row)
#define D_OUT   (D_C + D_F)    // 384

// Grid: one wave at occupancy 4 on 148 SMs = 592 CTAs.
// Byte-balanced split: coarse is 33.55MB of 302MB total (~11.1%).
#define NT_C    66
#define NT_F    526
#define NBLK    (NT_C + NT_F)

// TMA pipeline: 3 stages x 17KB (= 34 fine rows or 17 coarse rows).
#define NSTAGES      3
#define STAGE_BYTES  17408
#define DYN_SMEM     (NSTAGES * STAGE_BYTES)   // 52224 B -> exactly 4 CTAs/SM

// Self-restoring device state (zero at module load; finalize resets it).
__device__ float        g_scratch[B_SEG * D_OUT];
__device__ unsigned int g_count;

// ---------------------------------------------------------------------------
// mbarrier / bulk-copy PTX helpers (cta-scope)
// ---------------------------------------------------------------------------
__device__ __forceinline__ uint32_t smem_u32(const void* p) {
    return (uint32_t)__cvta_generic_to_shared(p);
}
__device__ __forceinline__ void mbar_init(uint32_t mbar, uint32_t count) {
    asm volatile("mbarrier.init.shared.b64 [%0], %1;" :: "r"(mbar), "r"(count) : "memory");
}
__device__ __forceinline__ void mbar_expect_tx(uint32_t mbar, uint32_t bytes) {
    asm volatile("mbarrier.arrive.expect_tx.shared.b64 _, [%0], %1;"
                 :: "r"(mbar), "r"(bytes) : "memory");
}
__device__ __forceinline__ void tma_bulk_g2s(uint32_t smem_dst, const void* gmem_src,
                                             uint32_t bytes, uint32_t mbar) {
    asm volatile("cp.async.bulk.shared::cta.global.mbarrier::complete_tx::bytes "
                 "[%0], [%1], %2, [%3];"
                 :: "r"(smem_dst), "l"(gmem_src), "r"(bytes), "r"(mbar) : "memory");
}
__device__ __forceinline__ void mbar_wait(uint32_t mbar, uint32_t parity) {
    uint32_t done;
    asm volatile(
        "{\n\t.reg .pred p;\n\t"
        "mbarrier.try_wait.parity.acquire.cta.shared::cta.b64 p, [%1], %2;\n\t"
        "selp.b32 %0, 1, 0, p;\n\t}"
        : "=r"(done) : "r"(mbar), "r"(parity) : "memory");
    if (!done) {
        asm volatile(
            "{\n\t.reg .pred P1;\n\t"
            "WAIT_LOOP_%=:\n\t"
            "mbarrier.try_wait.parity.acquire.cta.shared::cta.b64 P1, [%0], %1, 0x989680;\n\t"
            "@P1 bra.uni WAIT_DONE_%=;\n\t"
            "bra.uni WAIT_LOOP_%=;\n\t"
            "WAIT_DONE_%=:\n\t}"
            :: "r"(mbar), "r"(parity) : "memory");
    }
}

// ---------------------------------------------------------------------------
// Fused TMA-pipelined segment-sum + last-block finalize (single kernel).
// ---------------------------------------------------------------------------
__global__ void pare_tma_kernel(const char* __restrict__ feats_c,
                                const char* __restrict__ feats_f,
                                const int* __restrict__ lengths_c,
                                const int* __restrict__ lengths_f,
                                float* __restrict__ out,
                                int n_c, int n_f) {
    extern __shared__ __align__(1024) char stages[];
    __shared__ float4 shred[256];
    __shared__ int    scum[B_SEG + 1];
    __shared__ bool   sdone;
    __shared__ __align__(8) unsigned long long mbar_store[NSTAGES];

    const int  tid  = threadIdx.x;
    const bool is_c = (blockIdx.x < NT_C);

    const char* base          = is_c ? feats_c : feats_f;
    const int   rowbytes      = is_c ? 1024 : 512;
    const int   rows_per_stage= is_c ? 17 : 34;

    if (tid == 0) {
        const int* L = is_c ? lengths_c : lengths_f;
        int acc = 0;
        scum[0] = 0;
#pragma unroll
        for (int i = 0; i < B_SEG; ++i) { acc += L[i]; scum[i + 1] = acc; }
#pragma unroll
        for (int s = 0; s < NSTAGES; ++s) mbar_init(smem_u32(&mbar_store[s]), 1);
    }
    __syncthreads();

    // tile row range (byte-balanced, perfect-wave grid)
    int r0, r1;
    if (is_c) {
        int t = blockIdx.x;
        r0 = (int)(((long long)t)       * n_c / NT_C);
        r1 = (int)(((long long)(t + 1)) * n_c / NT_C);
    } else {
        int t = blockIdx.x - NT_C;
        r0 = (int)(((long long)t)       * n_f / NT_F);
        r1 = (int)(((long long)(t + 1)) * n_f / NT_F);
    }
    const int niter = (r1 - r0 + rows_per_stage - 1) / rows_per_stage;

    // prologue: fill the ring
    if (tid == 0) {
        for (int i = 0; i < NSTAGES && i < niter; ++i) {
            int a = r0 + i * rows_per_stage;
            int b = a + rows_per_stage; if (b > r1) b = r1;
            uint32_t bytes = (uint32_t)(b - a) * rowbytes;
            uint32_t mb = smem_u32(&mbar_store[i]);
            mbar_expect_tx(mb, bytes);
            tma_bulk_g2s(smem_u32(stages + i * STAGE_BYTES),
                         base + (size_t)a * rowbytes, bytes, mb);
        }
    }

    // consumer lane mapping
    const int c     = is_c ? (tid & 63) : (tid & 31);
    const int rr    = is_c ? (tid >> 6) : (tid >> 5);
    const int lanes = is_c ? 4 : 8;
    const int fcols = is_c ? 64 : 32;      // float4 per row
    const int obase = is_c ? 0 : D_C;      // column offset in output

    int seg = 0;
    while (scum[seg + 1] <= r0) ++seg;

    float4 acc = make_float4(0.f, 0.f, 0.f, 0.f);
    bool dirty = false;

    for (int i = 0; i < niter; ++i) {
        const int st = i % NSTAGES;
        const uint32_t ph = (uint32_t)((i / NSTAGES) & 1);
        mbar_wait(smem_u32(&mbar_store[st]), ph);

        int a = r0 + i * rows_per_stage;
        int b = a + rows_per_stage; if (b > r1) b = r1;
        const float4* sp = (const float4*)(stages + st * STAGE_BYTES);

        int g0 = a;
        while (g0 < b) {
            int e = scum[seg + 1]; if (e > b) e = b;
            for (int r = g0 + rr; r < e; r += lanes) {
                float4 v = sp[(r - a) * fcols + c];
                acc.x += v.x; acc.y += v.y; acc.z += v.z; acc.w += v.w;
            }
            dirty = true;
            if (e == scum[seg + 1]) {
                // block-uniform segment boundary: flush
                shred[tid] = acc;
                __syncthreads();
                if (rr == 0) {
                    float4 t = shred[c];
                    for (int k = 1; k < lanes; ++k) {
                        float4 v = shred[k * fcols + c];
                        t.x += v.x; t.y += v.y; t.z += v.z; t.w += v.w;
                    }
                    float* o = g_scratch + seg * D_OUT + obase + c * 4;
                    atomicAdd(o + 0, t.x);
                    atomicAdd(o + 1, t.y);
                    atomicAdd(o + 2, t.z);
                    atomicAdd(o + 3, t.w);
                }
                __syncthreads();
                acc = make_float4(0.f, 0.f, 0.f, 0.f);
                dirty = false;
                ++seg;
            }
            g0 = e;
        }

        __syncthreads();  // all consumers done with stage st
        const int ni = i + NSTAGES;
        if (tid == 0 && ni < niter) {
            int a2 = r0 + ni * rows_per_stage;
            int b2 = a2 + rows_per_stage; if (b2 > r1) b2 = r1;
            uint32_t bytes = (uint32_t)(b2 - a2) * rowbytes;
            uint32_t mb = smem_u32(&mbar_store[st]);
            mbar_expect_tx(mb, bytes);
            tma_bulk_g2s(smem_u32(stages + st * STAGE_BYTES),
                         base + (size_t)a2 * rowbytes, bytes, mb);
        }
    }

    // final flush of the trailing (unfinished) segment
    if (dirty) {
        shred[tid] = acc;
        __syncthreads();
        if (rr == 0) {
            float4 t = shred[c];
            for (int k = 1; k < lanes; ++k) {
                float4 v = shred[k * fcols + c];
                t.x += v.x; t.y += v.y; t.z += v.z; t.w += v.w;
            }
            float* o = g_scratch + seg * D_OUT + obase + c * 4;
            atomicAdd(o + 0, t.x);
            atomicAdd(o + 1, t.y);
            atomicAdd(o + 2, t.z);
            atomicAdd(o + 3, t.w);
        }
        __syncthreads();
    }

    // ---- last block to finish performs finalize + state reset ----
    if (tid == 0) {
        __threadfence();
        unsigned int old = atomicAdd(&g_count, 1u);
        sdone = (old == gridDim.x - 1);
    }
    __syncthreads();

    if (sdone) {
        __threadfence();
        for (int i = tid; i < B_SEG * D_OUT; i += 256) {
            int b = i / D_OUT;
            int d = i - b * D_OUT;
            int len = (d < D_C) ? lengths_c[b] : lengths_f[b];
            out[i] = g_scratch[i] / (float)len;
            g_scratch[i] = 0.0f;
        }
        __syncthreads();
        if (tid == 0) g_count = 0u;
    }
}

// ---------------------------------------------------------------------------
extern "C" void kernel_launch(void* const* d_in, const int* in_sizes, int n_in,
                              void* d_out, int out_size) {
    const float* feats_f   = (const float*)d_in[0];   // [524288, 128]
    const float* feats_c   = (const float*)d_in[1];   // [32768, 256]
    const int*   lengths_f = (const int*)d_in[2];     // [16]
    const int*   lengths_c = (const int*)d_in[3];     // [16]
    float* out = (float*)d_out;                       // [16, 384]

    const int n_f = in_sizes[0] / D_F;   // total fine rows
    const int n_c = in_sizes[1] / D_C;   // total coarse rows

    static bool attr_set = false;
    if (!attr_set) {
        cudaFuncSetAttribute(pare_tma_kernel,
                             cudaFuncAttributeMaxDynamicSharedMemorySize, DYN_SMEM);
        attr_set = true;
    }

    pare_tma_kernel<<<NBLK, 256, DYN_SMEM>>>((const char*)feats_c,
                                             (const char*)feats_f,
                                             lengths_c, lengths_f, out, n_c, n_f);
}